// round 15
// baseline (speedup 1.0000x reference)
#include <cuda_runtime.h>
#include <cuda_bf16.h>

// MQCNN layer, closed form (R0 derivation):
// Wires 0-3 get H -> uniform superposition over 16 control branches; the 12
// controlled-RY on wire 4 compose additively per branch; H + 24 controlled-U3
// act only on wires 5,6 and preserve the wire-4 marginal (U3_w is dead).
// <Z>_4 = (1/16) sum_b cos(theta_b) = 11 distinct cosines:
// z = (6cos(a) + cos(a+s1)+cos(a+s2)+cos(a+s3)+cos(a+s4)+cos(a+s5)
//    + cos(a+s1+s3)+cos(a+s2+s5)+cos(a+s2+s3+s4)+cos(a+s1+s4+s5)
//    + cos(a+s1+s2+s3+s4+s5)) / 16
//
// TERMINAL FIXED POINT (15 runs). ncu kernel samples on THIS binary:
// 5.02/5.06/5.12/5.31/5.44/6.11 us — single-shot profile jitter, not
// content. Harness dur = kernel + replay overhead, band 6.4-6.9,
// uncorrelated with all twelve kernel designs tried. Scanned & flat/worse:
// occ 13-71%, MLP 3-12, block {128,256,512}, 2x instr count,
// serial/tree/shfl reduction, streaming cache policy. Floor = one
// latency-limited 6.8MB DRAM pass + content-independent launch overhead;
// all pipes <=21%; traffic and MUFU count information-minimal.
// Shape: grid 512 x block 256, 1 output/thread, 6x coalesced LDG.64,
// exact-cover grid, CSE'd arguments, 20 regs.

#define CH_STRIDE (128 * 128)
#define N_OUT (32 * 64 * 64)

__global__ __launch_bounds__(256) void mqcnn_kernel(
    const float* __restrict__ x, float* __restrict__ out)
{
    int tid = blockIdx.x * blockDim.x + threadIdx.x;

    int k = tid & 63;
    int j = (tid >> 6) & 63;
    int b = tid >> 12;

    // x[b, 0, 2j, 2k]
    const float* base = x + (size_t)b * (3 * CH_STRIDE)
                          + (size_t)j * 256 + 2 * k;

    float2 c0r0 = *reinterpret_cast<const float2*>(base);
    float2 c0r1 = *reinterpret_cast<const float2*>(base + 128);
    float2 c1r0 = *reinterpret_cast<const float2*>(base + CH_STRIDE);
    float2 c1r1 = *reinterpret_cast<const float2*>(base + CH_STRIDE + 128);
    float2 c2r0 = *reinterpret_cast<const float2*>(base + 2 * CH_STRIDE);
    float2 c2r1 = *reinterpret_cast<const float2*>(base + 2 * CH_STRIDE + 128);

    float a  = c0r0.x + c1r0.x + c2r0.x;
    float s1 = c0r0.y + c1r1.x;
    float s2 = c0r1.x + c2r1.y;
    float s3 = c0r1.y;
    float s4 = c1r0.y + c2r1.x;
    float s5 = c1r1.y + c2r0.y;

    float a1  = a + s1;
    float a2  = a + s2;
    float s45 = s4 + s5;

    float sum = 6.0f * __cosf(a);
    sum += __cosf(a1);
    sum += __cosf(a2);
    sum += __cosf(a + s3);
    sum += __cosf(a + s4);
    sum += __cosf(a + s5);
    sum += __cosf(a1 + s3);             // a+s1+s3
    sum += __cosf(a2 + s5);             // a+s2+s5
    sum += __cosf(a2 + s3 + s4);        // a+s2+s3+s4
    sum += __cosf(a1 + s45);            // a+s1+s4+s5
    sum += __cosf(a1 + s2 + s3 + s45);  // a+all

    out[tid] = sum * 0.0625f;
}

extern "C" void kernel_launch(void* const* d_in, const int* in_sizes, int n_in,
                              void* d_out, int out_size) {
    const float* x = (const float*)d_in[0];   // [32,3,128,128] float32
    float* out = (float*)d_out;               // [32,1,64,64] float32
    mqcnn_kernel<<<N_OUT / 256, 256>>>(x, out);
}

// round 16
// speedup vs baseline: 1.0385x; 1.0385x over previous
#include <cuda_runtime.h>
#include <cuda_bf16.h>

// MQCNN layer, closed form (R0 derivation):
// Wires 0-3 get H -> uniform superposition over 16 control branches; the 12
// controlled-RY on wire 4 compose additively per branch; H + 24 controlled-U3
// act only on wires 5,6 and preserve the wire-4 marginal (U3_w is dead).
// <Z>_4 = (1/16) sum_b cos(theta_b) = 11 distinct cosines:
// z = (6cos(a) + cos(a+s1)+cos(a+s2)+cos(a+s3)+cos(a+s4)+cos(a+s5)
//    + cos(a+s1+s3)+cos(a+s2+s5)+cos(a+s2+s3+s4)+cos(a+s1+s4+s5)
//    + cos(a+s1+s2+s3+s4+s5)) / 16
//
// TERMINAL FIXED POINT (16 runs). ncu kernel samples on THIS binary:
// 5.02/5.06/5.12/5.31/5.38/5.44/6.11 us — single-shot profiler jitter.
// Harness dur band 6.40-6.91, uncorrelated with kernel content across all
// twelve designs tried. Scanned & flat/worse: occ 13-71%, MLP 3-12, block
// {128,256,512}, 2x instr count, serial/tree/shfl reduction, streaming
// cache policy. Math minimal: 11 MUFU.COS (sum-to-product pairing and
// angle-addition both cost more MUFU); traffic minimal (each byte once).
// Floor = one latency-limited 6.8MB DRAM pass + content-independent launch
// overhead; all pipes <=21%. Shape: grid 512 x block 256, 1 output/thread,
// 6x coalesced LDG.64, exact-cover grid, CSE'd arguments, 20 regs.

#define CH_STRIDE (128 * 128)
#define N_OUT (32 * 64 * 64)

__global__ __launch_bounds__(256) void mqcnn_kernel(
    const float* __restrict__ x, float* __restrict__ out)
{
    int tid = blockIdx.x * blockDim.x + threadIdx.x;

    int k = tid & 63;
    int j = (tid >> 6) & 63;
    int b = tid >> 12;

    // x[b, 0, 2j, 2k]
    const float* base = x + (size_t)b * (3 * CH_STRIDE)
                          + (size_t)j * 256 + 2 * k;

    float2 c0r0 = *reinterpret_cast<const float2*>(base);
    float2 c0r1 = *reinterpret_cast<const float2*>(base + 128);
    float2 c1r0 = *reinterpret_cast<const float2*>(base + CH_STRIDE);
    float2 c1r1 = *reinterpret_cast<const float2*>(base + CH_STRIDE + 128);
    float2 c2r0 = *reinterpret_cast<const float2*>(base + 2 * CH_STRIDE);
    float2 c2r1 = *reinterpret_cast<const float2*>(base + 2 * CH_STRIDE + 128);

    float a  = c0r0.x + c1r0.x + c2r0.x;
    float s1 = c0r0.y + c1r1.x;
    float s2 = c0r1.x + c2r1.y;
    float s3 = c0r1.y;
    float s4 = c1r0.y + c2r1.x;
    float s5 = c1r1.y + c2r0.y;

    float a1  = a + s1;
    float a2  = a + s2;
    float s45 = s4 + s5;

    float sum = 6.0f * __cosf(a);
    sum += __cosf(a1);
    sum += __cosf(a2);
    sum += __cosf(a + s3);
    sum += __cosf(a + s4);
    sum += __cosf(a + s5);
    sum += __cosf(a1 + s3);             // a+s1+s3
    sum += __cosf(a2 + s5);             // a+s2+s5
    sum += __cosf(a2 + s3 + s4);        // a+s2+s3+s4
    sum += __cosf(a1 + s45);            // a+s1+s4+s5
    sum += __cosf(a1 + s2 + s3 + s45);  // a+all

    out[tid] = sum * 0.0625f;
}

extern "C" void kernel_launch(void* const* d_in, const int* in_sizes, int n_in,
                              void* d_out, int out_size) {
    const float* x = (const float*)d_in[0];   // [32,3,128,128] float32
    float* out = (float*)d_out;               // [32,1,64,64] float32
    mqcnn_kernel<<<N_OUT / 256, 256>>>(x, out);
}